// round 16
// baseline (speedup 1.0000x reference)
#include <cuda_runtime.h>
#include <cstdint>

// SlideMean_Norm: out = x - clamped_sliding_mean(x, win=300) along T
// x: [32, 1, 16000, 80] float32
// window for t: [max(t-150,0), min(t+150, T-1)), count = e - s
//
// Persistent strip blocks, 620-row smem ring, cp.async prefetch.
// Span-prefix ring extended by warp-shuffle scan reading GMEM (L2-hot),
// so extension needs no cp.async arrival: 2 __syncthreads per iteration,
// with the per-thread wait_group overlapped by the extension's LDGs.

namespace {
constexpr int T     = 16000;
constexpr int F4    = 20;       // 80 floats = 20 float4 per full row
constexpr int HALF  = 150;
constexpr int LN    = 10;       // float4 lanes per half-row (160 B)
constexpr int SUB   = 10;       // output rows per thread per iter
constexpr int CB    = 160;      // rows per iteration
constexpr int NSUB  = CB / SUB; // 16
constexpr int NTHR  = LN * NSUB;          // 160 threads = 5 warps
constexpr int L     = 4000;               // strip length
constexpr int ITERS = L / CB;             // 25
constexpr int R     = 2 * CB + 2 * HALF;  // 620-row ring
constexpr int PRO   = CB + 2 * HALF;      // 460 prologue rows
constexpr int SPAN  = 10;                 // rows per span
constexpr int NSP_I = CB / SPAN;          // 16 spans per iter
constexpr int NSPAN_PRO = PRO / SPAN;     // 46
constexpr int SPR   = 64;                 // SP ring (pow2), live range 63
constexpr int WSP   = 2 * HALF / SPAN;    // 30 spans per window
constexpr float INV_FULL = 1.0f / 300.0f;
constexpr int SMEM_BYTES = (R * LN + SPR * LN) * (int)sizeof(float4); // 109,440 B
}

__device__ __forceinline__ float4 operator+(float4 a, float4 b) {
    return make_float4(a.x+b.x, a.y+b.y, a.z+b.z, a.w+b.w);
}
__device__ __forceinline__ float4 operator-(float4 a, float4 b) {
    return make_float4(a.x-b.x, a.y-b.y, a.z-b.z, a.w-b.w);
}
__device__ __forceinline__ void operator+=(float4& a, float4 b) { a = a + b; }
__device__ __forceinline__ void operator-=(float4& a, float4 b) { a = a - b; }
__device__ __forceinline__ float4 f4_fnms(float4 x, float4 ws, float inv) {
    return make_float4(fmaf(-ws.x, inv, x.x), fmaf(-ws.y, inv, x.y),
                       fmaf(-ws.z, inv, x.z), fmaf(-ws.w, inv, x.w));
}

__device__ __forceinline__ void cpa16(uint32_t dst, const float4* src, bool valid) {
    int sz = valid ? 16 : 0;   // src-size 0 => zero-fill
    asm volatile("cp.async.cg.shared.global [%0], [%1], 16, %2;\n"
                 :: "r"(dst), "l"(src), "r"(sz));
}
__device__ __forceinline__ void cpa_commit() {
    asm volatile("cp.async.commit_group;\n");
}
template <int N>
__device__ __forceinline__ void cpa_wait() {
    asm volatile("cp.async.wait_group %0;\n" :: "n"(N));
}

__global__ __launch_bounds__(NTHR, 2) void slide_ring_kernel(
    const float4* __restrict__ x, float4* __restrict__ out)
{
    extern __shared__ float4 smem[];
    float4* __restrict__ tile = smem;                   // [R][LN]
    float4* __restrict__ sp   = smem + R * LN;          // [SPR][LN] span prefix

    const int ln  = threadIdx.x;     // 0..9
    const int ty  = threadIdx.y;     // 0..15
    const int tid = ty * LN + ln;
    const int S0  = blockIdx.x * L;
    const int b   = blockIdx.y;
    const int hoff = blockIdx.z * LN;
    const int gfirst = S0 - HALF;

    const float4* __restrict__ xb = x   + (size_t)b * T * F4 + hoff;
    float4*       __restrict__ ob = out + (size_t)b * T * F4 + hoff;

    const uint32_t tile_sa = (uint32_t)__cvta_generic_to_shared(tile);
    const float4 zero = make_float4(0.f, 0.f, 0.f, 0.f);

    // ---- async load of local rows [l0, l0+nrows) into ring ----
    auto load_rows = [&](int l0, int nrows) {
        const int ring0 = l0 % R;
        for (int r = ty; r < nrows; r += NSUB) {
            int rg = ring0 + r; if (rg >= R) rg -= R;
            int g  = gfirst + l0 + r;
            bool v = (g >= 0) & (g < T);
            cpa16(tile_sa + (uint32_t)(rg * LN + ln) * 16,
                  xb + (size_t)(v ? g : 0) * F4 + ln, v);
        }
    };

    // ---- span extension from GMEM: build <=16 10-row spans starting at
    //      local row l0 (global gfirst+l0), inclusive-scan in registers
    //      (width-16 shfl segments), append to SP after SP[J]. No tile
    //      dependency, no internal barriers. ----
    auto extend_spans = [&](int l0, int nspans, int J) {
        const int lane = tid & 31;
        const int w    = tid >> 5;            // 0..4
        const int j    = lane & 15;           // span index
        const int ln2  = 2 * w + (lane >> 4); // 0..9
        float4 s = zero;
        if (j < nspans) {
            const int g0 = gfirst + l0 + j * SPAN;
            const float4* __restrict__ gp = xb + (size_t)g0 * F4 + ln2;
            #pragma unroll
            for (int k = 0; k < SPAN; ++k) {
                int g = g0 + k;
                if (g >= 0 && g < T) s += gp[(size_t)k * F4];
            }
        }
        #pragma unroll
        for (int d = 1; d < 16; d <<= 1) {
            float4 v;
            v.x = __shfl_up_sync(0xffffffffu, s.x, d, 16);
            v.y = __shfl_up_sync(0xffffffffu, s.y, d, 16);
            v.z = __shfl_up_sync(0xffffffffu, s.z, d, 16);
            v.w = __shfl_up_sync(0xffffffffu, s.w, d, 16);
            if (j >= d) s += v;
        }
        float4 base = sp[(J & (SPR - 1)) * LN + ln2];
        if (j < nspans)
            sp[((J + 1 + j) & (SPR - 1)) * LN + ln2] = base + s;
    };

    // ---- prologue: loads in flight while spans built from gmem ----
    load_rows(0, PRO);        cpa_commit();   // g1: rows [0,460)
    load_rows(PRO, CB);       cpa_commit();   // g2: rows [460,620)
    if (tid < LN) sp[tid] = zero;             // SP[0] = 0
    __syncthreads();
    extend_spans(0,   NSP_I, 0);   __syncthreads();  // SP[1..16]
    extend_spans(160, NSP_I, 16);  __syncthreads();  // SP[17..32]
    extend_spans(320, NSPAN_PRO - 2 * NSP_I, 32);    // SP[33..46]
    cpa_wait<1>();                            // own g1 slices done
    __syncthreads();                          // publish rows [0,460) + SP

    for (int i = 0; i < ITERS; ++i) {
        // ---- compute outputs [S0+i*CB, +CB) ----
        {
            const int tg0 = S0 + i * CB + ty * SUB;
            const int m0  = i * NSP_I + ty;

            float4 ws = sp[((m0 + WSP) & (SPR - 1)) * LN + ln]
                      - sp[(m0 & (SPR - 1)) * LN + ln];

            int rc = (i * CB + ty * SUB + HALF) % R;   // multiple of 10
            int rl = rc + HALF; if (rl >= R) rl -= R;
            int rt = rc - HALF; if (rt < 0)  rt += R;
            // 10-row segments never wrap (bases multiples of 10, 10 | R)
            const float4* __restrict__ pc = tile + rc * LN + ln;
            const float4* __restrict__ pl = tile + rl * LN + ln;
            const float4* __restrict__ pt = tile + rt * LN + ln;
            float4* __restrict__ op = ob + (size_t)tg0 * F4 + ln;

            const bool lo = (tg0 < HALF);
            const bool hi = (tg0 >= T - HALF);
            if (!lo && !hi) {
                #pragma unroll
                for (int k = 0; k < SUB; ++k) {
                    float4 xv = pc[k * LN];
                    __stcs(op + (size_t)k * F4, f4_fnms(xv, ws, INV_FULL));
                    ws += pl[k * LN] - pt[k * LN];
                }
            } else {
                float4 xl = zero;
                if (hi) xl = tile[((T - 1 - gfirst) % R) * LN + ln];
                #pragma unroll
                for (int k = 0; k < SUB; ++k) {
                    const int t = tg0 + k;
                    int s = t - HALF; if (s < 0) s = 0;
                    int e = t + HALF; if (e > T - 1) e = T - 1;
                    float inv = 1.0f / (float)(e - s);
                    float4 wsc = ws;
                    if (t >= T - HALF) wsc -= xl;
                    float4 xv = pc[k * LN];
                    __stcs(op + (size_t)k * F4, f4_fnms(xv, wsc, inv));
                    ws += pl[k * LN] - pt[k * LN];
                }
            }
        }

        // ---- pipeline turn-over: 2 barriers, wait hidden behind extend ----
        if (i + 1 < ITERS) {
            __syncthreads();                 // compute-i readers done (WAR)
            const bool more = (i + 2 < ITERS);
            if (more) {
                load_rows(PRO + (i + 1) * CB, CB);   // slots of rows [160i,+160)
                cpa_commit();
            }
            extend_spans(PRO + i * CB, NSP_I, NSPAN_PRO + i * NSP_I); // gmem
            if (more) cpa_wait<1>(); else cpa_wait<0>();
            __syncthreads();                 // rows(i+1) + SP visible to all
        }
    }
}

extern "C" void kernel_launch(void* const* d_in, const int* in_sizes, int n_in,
                              void* d_out, int out_size)
{
    const float4* x = (const float4*)d_in[0];
    float4* out = (float4*)d_out;

    static bool attr_set = false;
    if (!attr_set) {
        cudaFuncSetAttribute(slide_ring_kernel,
                             cudaFuncAttributeMaxDynamicSharedMemorySize,
                             SMEM_BYTES);
        attr_set = true;
    }

    dim3 blk(LN, NSUB);            // 160 threads = 5 warps
    dim3 grid(T / L, 32, 2);       // 4 strips x 32 batches x 2 halves = 256
    slide_ring_kernel<<<grid, blk, SMEM_BYTES>>>(x, out);
}

// round 17
// speedup vs baseline: 2.0944x; 2.0944x over previous
#include <cuda_runtime.h>
#include <cstdint>

// SlideMean_Norm: out = x - clamped_sliding_mean(x, win=300) along T
// x: [32, 1, 16000, 80] float32
// window for t: [max(t-150,0), min(t+150, T-1)), count = e - s
//
// Persistent strip blocks, 620-row smem ring, cp.async prefetch issued
// BEFORE the wait so one group is always in flight. Span-prefix ring
// extended by warp-shuffle scan reading the SMEM tile (coalesced, no
// internal barriers): 3 __syncthreads per iteration.

namespace {
constexpr int T     = 16000;
constexpr int F4    = 20;       // 80 floats = 20 float4 per full row
constexpr int HALF  = 150;
constexpr int LN    = 10;       // float4 lanes per half-row (160 B)
constexpr int SUB   = 10;       // output rows per thread per iter
constexpr int CB    = 160;      // rows per iteration
constexpr int NSUB  = CB / SUB; // 16
constexpr int NTHR  = LN * NSUB;          // 160 threads = 5 warps
constexpr int L     = 4000;               // strip length
constexpr int ITERS = L / CB;             // 25
constexpr int R     = 2 * CB + 2 * HALF;  // 620-row ring
constexpr int PRO   = CB + 2 * HALF;      // 460 prologue rows
constexpr int SPAN  = 10;                 // rows per span
constexpr int NSP_I = CB / SPAN;          // 16 spans per iter
constexpr int NSPAN_PRO = PRO / SPAN;     // 46
constexpr int SPR   = 64;                 // SP ring (pow2), live range 63
constexpr int WSP   = 2 * HALF / SPAN;    // 30 spans per window
constexpr float INV_FULL = 1.0f / 300.0f;
constexpr int SMEM_BYTES = (R * LN + SPR * LN) * (int)sizeof(float4); // 109,440 B
}

__device__ __forceinline__ float4 operator+(float4 a, float4 b) {
    return make_float4(a.x+b.x, a.y+b.y, a.z+b.z, a.w+b.w);
}
__device__ __forceinline__ float4 operator-(float4 a, float4 b) {
    return make_float4(a.x-b.x, a.y-b.y, a.z-b.z, a.w-b.w);
}
__device__ __forceinline__ void operator+=(float4& a, float4 b) { a = a + b; }
__device__ __forceinline__ void operator-=(float4& a, float4 b) { a = a - b; }
__device__ __forceinline__ float4 f4_fnms(float4 x, float4 ws, float inv) {
    return make_float4(fmaf(-ws.x, inv, x.x), fmaf(-ws.y, inv, x.y),
                       fmaf(-ws.z, inv, x.z), fmaf(-ws.w, inv, x.w));
}

__device__ __forceinline__ void cpa16(uint32_t dst, const float4* src, bool valid) {
    int sz = valid ? 16 : 0;   // src-size 0 => zero-fill
    asm volatile("cp.async.cg.shared.global [%0], [%1], 16, %2;\n"
                 :: "r"(dst), "l"(src), "r"(sz));
}
__device__ __forceinline__ void cpa_commit() {
    asm volatile("cp.async.commit_group;\n");
}
template <int N>
__device__ __forceinline__ void cpa_wait() {
    asm volatile("cp.async.wait_group %0;\n" :: "n"(N));
}

__global__ __launch_bounds__(NTHR, 2) void slide_ring_kernel(
    const float4* __restrict__ x, float4* __restrict__ out)
{
    extern __shared__ float4 smem[];
    float4* __restrict__ tile = smem;                   // [R][LN]
    float4* __restrict__ sp   = smem + R * LN;          // [SPR][LN] span prefix

    const int ln  = threadIdx.x;     // 0..9
    const int ty  = threadIdx.y;     // 0..15
    const int tid = ty * LN + ln;
    const int S0  = blockIdx.x * L;
    const int b   = blockIdx.y;
    const int hoff = blockIdx.z * LN;
    const int gfirst = S0 - HALF;

    const float4* __restrict__ xb = x   + (size_t)b * T * F4 + hoff;
    float4*       __restrict__ ob = out + (size_t)b * T * F4 + hoff;

    const uint32_t tile_sa = (uint32_t)__cvta_generic_to_shared(tile);
    const float4 zero = make_float4(0.f, 0.f, 0.f, 0.f);

    // ---- async load of local rows [l0, l0+nrows) into ring ----
    auto load_rows = [&](int l0, int nrows) {
        const int ring0 = l0 % R;
        for (int r = ty; r < nrows; r += NSUB) {
            int rg = ring0 + r; if (rg >= R) rg -= R;
            int g  = gfirst + l0 + r;
            bool v = (g >= 0) & (g < T);
            cpa16(tile_sa + (uint32_t)(rg * LN + ln) * 16,
                  xb + (size_t)(v ? g : 0) * F4 + ln, v);
        }
    };

    // ---- warp-shuffle span extension: build <=16 10-row spans starting at
    //      local row l0 (already resident in tile), inclusive-scan them in
    //      registers (width-16 shfl segments), append to SP after SP[J].
    //      NO internal barriers; caller fences tile before, SP after. ----
    auto extend_spans = [&](int l0, int nspans, int J) {
        const int lane = tid & 31;
        const int w    = tid >> 5;            // 0..4
        const int j    = lane & 15;           // span index
        const int ln2  = 2 * w + (lane >> 4); // 0..9
        float4 s = zero;
        if (j < nspans) {
            int rb = (l0 % R) + j * SPAN; if (rb >= R) rb -= R;
            const float4* __restrict__ tp = tile + rb * LN + ln2;
            #pragma unroll
            for (int k = 0; k < SPAN; ++k) s += tp[k * LN];
        }
        #pragma unroll
        for (int d = 1; d < 16; d <<= 1) {
            float4 v;
            v.x = __shfl_up_sync(0xffffffffu, s.x, d, 16);
            v.y = __shfl_up_sync(0xffffffffu, s.y, d, 16);
            v.z = __shfl_up_sync(0xffffffffu, s.z, d, 16);
            v.w = __shfl_up_sync(0xffffffffu, s.w, d, 16);
            if (j >= d) s += v;
        }
        float4 base = sp[(J & (SPR - 1)) * LN + ln2];
        if (j < nspans)
            sp[((J + 1 + j) & (SPR - 1)) * LN + ln2] = base + s;
    };

    // ---- prologue ----
    load_rows(0, PRO);        cpa_commit();   // g1: rows [0,460)
    load_rows(PRO, CB);       cpa_commit();   // g2: rows [460,620)
    cpa_wait<1>();                            // own g1 slices done
    __syncthreads();                          // rows [0,460) visible to all
    if (tid < LN) sp[tid] = zero;             // SP[0] = 0
    __syncthreads();
    extend_spans(0,   NSP_I, 0);   __syncthreads();  // SP[1..16]
    extend_spans(160, NSP_I, 16);  __syncthreads();  // SP[17..32]
    extend_spans(320, NSPAN_PRO - 2 * NSP_I, 32);    // SP[33..46]
    __syncthreads();

    for (int i = 0; i < ITERS; ++i) {
        // ---- compute outputs [S0+i*CB, +CB) ----
        {
            const int tg0 = S0 + i * CB + ty * SUB;
            const int m0  = i * NSP_I + ty;

            float4 ws = sp[((m0 + WSP) & (SPR - 1)) * LN + ln]
                      - sp[(m0 & (SPR - 1)) * LN + ln];

            int rc = (i * CB + ty * SUB + HALF) % R;   // multiple of 10
            int rl = rc + HALF; if (rl >= R) rl -= R;
            int rt = rc - HALF; if (rt < 0)  rt += R;
            // 10-row segments never wrap (bases multiples of 10, 10 | R)
            const float4* __restrict__ pc = tile + rc * LN + ln;
            const float4* __restrict__ pl = tile + rl * LN + ln;
            const float4* __restrict__ pt = tile + rt * LN + ln;
            float4* __restrict__ op = ob + (size_t)tg0 * F4 + ln;

            const bool lo = (tg0 < HALF);
            const bool hi = (tg0 >= T - HALF);
            if (!lo && !hi) {
                #pragma unroll
                for (int k = 0; k < SUB; ++k) {
                    float4 xv = pc[k * LN];
                    __stcs(op + (size_t)k * F4, f4_fnms(xv, ws, INV_FULL));
                    ws += pl[k * LN] - pt[k * LN];
                }
            } else {
                float4 xl = zero;
                if (hi) xl = tile[((T - 1 - gfirst) % R) * LN + ln];
                #pragma unroll
                for (int k = 0; k < SUB; ++k) {
                    const int t = tg0 + k;
                    int s = t - HALF; if (s < 0) s = 0;
                    int e = t + HALF; if (e > T - 1) e = T - 1;
                    float inv = 1.0f / (float)(e - s);
                    float4 wsc = ws;
                    if (t >= T - HALF) wsc -= xl;
                    float4 xv = pc[k * LN];
                    __stcs(op + (size_t)k * F4, f4_fnms(xv, wsc, inv));
                    ws += pl[k * LN] - pt[k * LN];
                }
            }
        }

        // ---- pipeline turn-over: 3 barriers, DRAM never drained ----
        if (i + 1 < ITERS) {
            __syncthreads();                 // WAR: compute-i readers done
            const bool more = (i + 2 < ITERS);
            if (more) {
                load_rows(PRO + (i + 1) * CB, CB);   // overwrites slots of
                cpa_commit();                        //   local rows [i*CB,+CB)
                cpa_wait<1>();               // rows i+1 arrived; i+2 flying
            } else {
                cpa_wait<0>();
            }
            __syncthreads();                 // rows i+1 visible to all threads
            extend_spans(PRO + i * CB, NSP_I, NSPAN_PRO + i * NSP_I);
            __syncthreads();                 // SP visible
        }
    }
}

extern "C" void kernel_launch(void* const* d_in, const int* in_sizes, int n_in,
                              void* d_out, int out_size)
{
    const float4* x = (const float4*)d_in[0];
    float4* out = (float4*)d_out;

    static bool attr_set = false;
    if (!attr_set) {
        cudaFuncSetAttribute(slide_ring_kernel,
                             cudaFuncAttributeMaxDynamicSharedMemorySize,
                             SMEM_BYTES);
        attr_set = true;
    }

    dim3 blk(LN, NSUB);            // 160 threads = 5 warps
    dim3 grid(T / L, 32, 2);       // 4 strips x 32 batches x 2 halves = 256
    slide_ring_kernel<<<grid, blk, SMEM_BYTES>>>(x, out);
}